// round 2
// baseline (speedup 1.0000x reference)
#include <cuda_runtime.h>

// AccRNNCell: B=512, T=512, F=64, U=512, P=32, L=3
// Persistent batch-parallel kernel: 128 CTAs x 4 batch rows, all recurrent
// state in SMEM, weights streamed from L2 each step. No inter-CTA sync needed.

#define UU 512
#define FF 64
#define PP 32
#define NL 3
#define BT 4      // batch rows per CTA
#define TPB 256
#define TT 512
#define BB 512

__global__ void __launch_bounds__(TPB, 1) accrnn_persistent(
    const float* __restrict__ x,
    const float* __restrict__ WA,  const float* __restrict__ bA,
    const float* __restrict__ WB0, const float* __restrict__ bB0,
    const float* __restrict__ WBr, const float* __restrict__ bBr,
    const float* __restrict__ WC,  const float* __restrict__ bC,
    const float* __restrict__ Wout, const float* __restrict__ bout,
    float* __restrict__ out)
{
    // Transposed layouts: [k][row] so activation reads are one LDS.128 broadcast.
    __shared__ float hsT[NL][UU][BT];   // hidden states, 24 KB
    __shared__ float prevT[UU][BT];     // current layer input (width 96 or 512)
    __shared__ float nsT[UU][BT];       // new_state scratch
    __shared__ float accS[BT][PP];      // running accumulator

    const int tid = threadIdx.x;
    const int b0  = blockIdx.x * BT;
    const int j0  = tid * 2;            // this thread's output column pair

    // Zero-init recurrent state (fresh every launch -> deterministic).
    for (int i = tid; i < NL * UU * BT; i += TPB) ((float*)hsT)[i] = 0.f;
    for (int i = tid; i < BT * PP;      i += TPB) ((float*)accS)[i] = 0.f;
    __syncthreads();

    const int xr = tid >> 6;            // 0..3   (BT*FF == TPB exactly)
    const int xf = tid & 63;            // 0..63
    const float* xrow = x + ((size_t)(b0 + xr) * TT) * FF + xf;

    for (int t = 0; t < TT; ++t) {
        // ---- build prev = concat(x_t, acc), transposed ----
        prevT[xf][xr] = xrow[(size_t)t * FF];
        if (tid < BT * PP) {
            int r = tid >> 5, p = tid & 31;
            prevT[FF + p][r] = accS[r][p];
        }
        __syncthreads();

        #pragma unroll
        for (int l = 0; l < NL; ++l) {
            const float* Wa = WA + (size_t)l * UU * UU + j0;
            const float* Wb = (l == 0) ? (WB0 + j0)
                                       : (WBr + (size_t)(l - 1) * UU * UU + j0);
            const int Kb = (l == 0) ? (FF + PP) : UU;

            float bv0 = bA[l * UU + j0]     + ((l == 0) ? bB0[j0]     : bBr[(l - 1) * UU + j0]);
            float bv1 = bA[l * UU + j0 + 1] + ((l == 0) ? bB0[j0 + 1] : bBr[(l - 1) * UU + j0 + 1]);

            float a00 = bv0, a01 = bv0, a02 = bv0, a03 = bv0;
            float a10 = bv1, a11 = bv1, a12 = bv1, a13 = bv1;

            // latent_state = hs[l] @ WA[l]
            #pragma unroll 8
            for (int k = 0; k < UU; ++k) {
                float2 w = *reinterpret_cast<const float2*>(Wa + (size_t)k * UU);
                float4 h = *reinterpret_cast<const float4*>(&hsT[l][k][0]);
                a00 = fmaf(w.x, h.x, a00); a01 = fmaf(w.x, h.y, a01);
                a02 = fmaf(w.x, h.z, a02); a03 = fmaf(w.x, h.w, a03);
                a10 = fmaf(w.y, h.x, a10); a11 = fmaf(w.y, h.y, a11);
                a12 = fmaf(w.y, h.z, a12); a13 = fmaf(w.y, h.w, a13);
            }
            // latent_input = prev @ WB
            #pragma unroll 8
            for (int k = 0; k < Kb; ++k) {
                float2 w = *reinterpret_cast<const float2*>(Wb + (size_t)k * UU);
                float4 p = *reinterpret_cast<const float4*>(&prevT[k][0]);
                a00 = fmaf(w.x, p.x, a00); a01 = fmaf(w.x, p.y, a01);
                a02 = fmaf(w.x, p.z, a02); a03 = fmaf(w.x, p.w, a03);
                a10 = fmaf(w.y, p.x, a10); a11 = fmaf(w.y, p.y, a11);
                a12 = fmaf(w.y, p.z, a12); a13 = fmaf(w.y, p.w, a13);
            }
            *reinterpret_cast<float4*>(&nsT[j0][0])     = make_float4(a00, a01, a02, a03);
            *reinterpret_cast<float4*>(&nsT[j0 + 1][0]) = make_float4(a10, a11, a12, a13);
            __syncthreads();   // nsT complete; old prevT / hsT[l] fully consumed

            // prev' = new_state @ WC[l] + bC[l]
            const float* Wc = WC + (size_t)l * UU * UU + j0;
            float cb0 = bC[l * UU + j0], cb1 = bC[l * UU + j0 + 1];
            float c00 = cb0, c01 = cb0, c02 = cb0, c03 = cb0;
            float c10 = cb1, c11 = cb1, c12 = cb1, c13 = cb1;
            #pragma unroll 8
            for (int k = 0; k < UU; ++k) {
                float2 w = *reinterpret_cast<const float2*>(Wc + (size_t)k * UU);
                float4 n = *reinterpret_cast<const float4*>(&nsT[k][0]);
                c00 = fmaf(w.x, n.x, c00); c01 = fmaf(w.x, n.y, c01);
                c02 = fmaf(w.x, n.z, c02); c03 = fmaf(w.x, n.w, c03);
                c10 = fmaf(w.y, n.x, c10); c11 = fmaf(w.y, n.y, c11);
                c12 = fmaf(w.y, n.z, c12); c13 = fmaf(w.y, n.w, c13);
            }
            // commit hidden state; overwrite prev for next layer
            *reinterpret_cast<float4*>(&hsT[l][j0][0])     = *reinterpret_cast<const float4*>(&nsT[j0][0]);
            *reinterpret_cast<float4*>(&hsT[l][j0 + 1][0]) = *reinterpret_cast<const float4*>(&nsT[j0 + 1][0]);
            *reinterpret_cast<float4*>(&prevT[j0][0])      = make_float4(c00, c01, c02, c03);
            *reinterpret_cast<float4*>(&prevT[j0 + 1][0])  = make_float4(c10, c11, c12, c13);
            __syncthreads();
        }

        // ---- res = prev @ Wout + bout ; acc += res ; emit res ----
        if (tid < BT * PP) {
            int r = tid >> 5, p = tid & 31;
            float s = bout[p];
            #pragma unroll 8
            for (int k = 0; k < UU; ++k)
                s = fmaf(prevT[k][r], Wout[k * PP + p], s);
            accS[r][p] += s;
            out[((size_t)(b0 + r) * TT + t) * PP + p] = s;
        }
        __syncthreads();
    }
}

extern "C" void kernel_launch(void* const* d_in, const int* in_sizes, int n_in,
                              void* d_out, int out_size)
{
    const float* x    = (const float*)d_in[0];
    const float* WA   = (const float*)d_in[1];
    const float* bA   = (const float*)d_in[2];
    const float* WB0  = (const float*)d_in[3];
    const float* bB0  = (const float*)d_in[4];
    const float* WBr  = (const float*)d_in[5];
    const float* bBr  = (const float*)d_in[6];
    const float* WC   = (const float*)d_in[7];
    const float* bC   = (const float*)d_in[8];
    const float* Wout = (const float*)d_in[9];
    const float* bout = (const float*)d_in[10];
    float* out = (float*)d_out;

    accrnn_persistent<<<BB / BT, TPB>>>(x, WA, bA, WB0, bB0, WBr, bBr,
                                        WC, bC, Wout, bout, out);
}

// round 3
// speedup vs baseline: 1.2396x; 1.2396x over previous
#include <cuda_runtime.h>

// AccRNNCell: B=512, T=512, F=64, U=512, P=32, L=3
// Persistent batch-parallel kernel, 128 CTAs x 4 batch rows.
// f32x2 packed FMA (FFMA2): thread owns 2 adjacent output columns x 4 rows;
// weight LDG.64 is a natural f32x2 pair, SMEM state is stored DUPLICATED
// ((v,v) pairs) so the activation operand is a natural broadcast LDS.128.

#define UU 512
#define FF 64
#define PP 32
#define NL 3
#define BT 4
#define TPB 256
#define TT 512
#define BB 512

#define SMEM_FLOATS (NL*UU*8 + UU*8 + UU*8 + BT*PP + TPB)
#define SMEM_BYTES  (SMEM_FLOATS * 4)

__device__ __forceinline__ unsigned long long pack2(float x, float y) {
    unsigned long long v;
    asm("mov.b64 %0, {%1, %2};" : "=l"(v) : "f"(x), "f"(y));
    return v;
}
__device__ __forceinline__ void unpack2(unsigned long long v, float& x, float& y) {
    asm("mov.b64 {%0, %1}, %2;" : "=f"(x), "=f"(y) : "l"(v));
}
// store 4 row-values duplicated: (v0,v0,v1,v1,v2,v2,v3,v3)
__device__ __forceinline__ void store_dup(float* dst, float v0, float v1, float v2, float v3) {
    *reinterpret_cast<float4*>(dst)     = make_float4(v0, v0, v1, v1);
    *reinterpret_cast<float4*>(dst + 4) = make_float4(v2, v2, v3, v3);
}

// acc[r] (r=0..3) is an f32x2 pair over (col j0, col j0+1) for batch row r.
// W: weight column base (W + j0), row stride UU. S: duplicated state, 8 floats/k.
template<int K>
__device__ __forceinline__ void gemmK(const float* __restrict__ W,
                                      const float* __restrict__ S,
                                      unsigned long long* __restrict__ a)
{
#pragma unroll 16
    for (int k = 0; k < K; ++k) {
        unsigned long long w = *reinterpret_cast<const unsigned long long*>(W + k * UU);
        ulonglong2 h01 = *reinterpret_cast<const ulonglong2*>(S + k * 8);
        ulonglong2 h23 = *reinterpret_cast<const ulonglong2*>(S + k * 8 + 4);
        asm("fma.rn.f32x2 %0, %1, %2, %0;" : "+l"(a[0]) : "l"(w), "l"(h01.x));
        asm("fma.rn.f32x2 %0, %1, %2, %0;" : "+l"(a[1]) : "l"(w), "l"(h01.y));
        asm("fma.rn.f32x2 %0, %1, %2, %0;" : "+l"(a[2]) : "l"(w), "l"(h23.x));
        asm("fma.rn.f32x2 %0, %1, %2, %0;" : "+l"(a[3]) : "l"(w), "l"(h23.y));
    }
}

__global__ void __launch_bounds__(TPB, 1) accrnn_persistent(
    const float* __restrict__ x,
    const float* __restrict__ WA,  const float* __restrict__ bA,
    const float* __restrict__ WB0, const float* __restrict__ bB0,
    const float* __restrict__ WBr, const float* __restrict__ bBr,
    const float* __restrict__ WC,  const float* __restrict__ bC,
    const float* __restrict__ Wout, const float* __restrict__ bout,
    float* __restrict__ out)
{
    extern __shared__ float smem[];
    float* hsD   = smem;                      // [NL][UU][8] duplicated, 48 KB
    float* prevD = hsD + NL * UU * 8;         // [UU][8] duplicated, 16 KB
    float* nsD   = prevD + UU * 8;            // [UU][8] duplicated, 16 KB
    float* accS  = nsD + UU * 8;              // [BT][PP]
    float* wpart = accS + BT * PP;            // [TPB] split-k partials

    const int tid = threadIdx.x;
    const int b0  = blockIdx.x * BT;
    const int j0  = tid * 2;

    // zero-init recurrent state (fresh every launch -> deterministic)
    for (int i = tid; i < NL * UU * 8; i += TPB) hsD[i] = 0.f;
    if (tid < BT * PP) accS[tid] = 0.f;
    __syncthreads();

    const int xr = tid >> 6;            // 0..3  (BT*FF == TPB)
    const int xf = tid & 63;            // 0..63
    const float* xrow = x + ((size_t)(b0 + xr) * TT) * FF + xf;

    for (int t = 0; t < TT; ++t) {
        // ---- prevD = concat(x_t, acc), duplicated ----
        {
            float v = xrow[(size_t)t * FF];
            *reinterpret_cast<float2*>(&prevD[xf * 8 + 2 * xr]) = make_float2(v, v);
        }
        if (tid < BT * PP) {
            int r = tid >> 5, p = tid & 31;
            float v = accS[tid];
            *reinterpret_cast<float2*>(&prevD[(FF + p) * 8 + 2 * r]) = make_float2(v, v);
        }
        __syncthreads();

        #pragma unroll
        for (int l = 0; l < NL; ++l) {
            const float* Wa = WA + (size_t)l * UU * UU + j0;
            const float* Wb = (l == 0) ? (WB0 + j0)
                                       : (WBr + (size_t)(l - 1) * UU * UU + j0);

            float bv0 = bA[l * UU + j0]     + ((l == 0) ? bB0[j0]     : bBr[(l - 1) * UU + j0]);
            float bv1 = bA[l * UU + j0 + 1] + ((l == 0) ? bB0[j0 + 1] : bBr[(l - 1) * UU + j0 + 1]);

            unsigned long long a[4];
            a[0] = a[1] = a[2] = a[3] = pack2(bv0, bv1);

            gemmK<UU>(Wa, hsD + l * UU * 8, a);          // latent_state = hs[l] @ WA[l]
            if (l == 0) gemmK<FF + PP>(Wb, prevD, a);    // latent_input = prev @ WB
            else        gemmK<UU>(Wb, prevD, a);

            float n00, n10, n01, n11, n02, n12, n03, n13;
            unpack2(a[0], n00, n10); unpack2(a[1], n01, n11);
            unpack2(a[2], n02, n12); unpack2(a[3], n03, n13);
            store_dup(nsD + j0 * 8,       n00, n01, n02, n03);
            store_dup(nsD + (j0 + 1) * 8, n10, n11, n12, n13);
            __syncthreads();   // nsD complete; old prevD / hsD[l] fully consumed

            // prev' = new_state @ WC[l] + bC[l]
            const float* Wc = WC + (size_t)l * UU * UU + j0;
            unsigned long long c[4];
            c[0] = c[1] = c[2] = c[3] = pack2(bC[l * UU + j0], bC[l * UU + j0 + 1]);
            gemmK<UU>(Wc, nsD, c);

            // commit hidden state from registers; overwrite prevD
            store_dup(hsD + (l * UU + j0) * 8,       n00, n01, n02, n03);
            store_dup(hsD + (l * UU + j0 + 1) * 8,   n10, n11, n12, n13);
            float c00, c10, c01, c11, c02, c12, c03, c13;
            unpack2(c[0], c00, c10); unpack2(c[1], c01, c11);
            unpack2(c[2], c02, c12); unpack2(c[3], c03, c13);
            store_dup(prevD + j0 * 8,       c00, c01, c02, c03);
            store_dup(prevD + (j0 + 1) * 8, c10, c11, c12, c13);
            __syncthreads();
        }

        // ---- res = prev @ Wout + bout ; acc += res ; emit ----
        {
            int ks = tid >> 7;           // split-k: 0 or 1
            int rp = tid & 127;
            int r = rp >> 5, p = rp & 31;
            float s = (ks == 0) ? bout[p] : 0.f;
            int kbeg = ks * (UU / 2);
            #pragma unroll 8
            for (int k = kbeg; k < kbeg + UU / 2; ++k)
                s = fmaf(prevD[k * 8 + 2 * r], Wout[k * PP + p], s);
            wpart[tid] = s;
        }
        __syncthreads();
        if (tid < BT * PP) {
            int r = tid >> 5, p = tid & 31;
            float tot = wpart[tid] + wpart[tid + 128];
            accS[tid] += tot;
            out[((size_t)(b0 + r) * TT + t) * PP + p] = tot;
        }
        __syncthreads();
    }
}

extern "C" void kernel_launch(void* const* d_in, const int* in_sizes, int n_in,
                              void* d_out, int out_size)
{
    const float* x    = (const float*)d_in[0];
    const float* WA   = (const float*)d_in[1];
    const float* bA   = (const float*)d_in[2];
    const float* WB0  = (const float*)d_in[3];
    const float* bB0  = (const float*)d_in[4];
    const float* WBr  = (const float*)d_in[5];
    const float* bBr  = (const float*)d_in[6];
    const float* WC   = (const float*)d_in[7];
    const float* bC   = (const float*)d_in[8];
    const float* Wout = (const float*)d_in[9];
    const float* bout = (const float*)d_in[10];
    float* out = (float*)d_out;

    cudaFuncSetAttribute(accrnn_persistent,
                         cudaFuncAttributeMaxDynamicSharedMemorySize, SMEM_BYTES);
    accrnn_persistent<<<BB / BT, TPB, SMEM_BYTES>>>(x, WA, bA, WB0, bB0, WBr, bBr,
                                                    WC, bC, Wout, bout, out);
}